// round 3
// baseline (speedup 1.0000x reference)
#include <cuda_runtime.h>
#include <math.h>

#define BATCH   4
#define SEQLEN  2048
#define DMODEL  1024
#define DINNER  2048
#define DSTATE  64
#define NHEADS  32
#define HEADDIM 64
#define CONVDIM 2176          // DINNER + 2*DSTATE
#define DIP     4256          // 2*DINNER + 2*DSTATE + NHEADS
#define MROWS   (BATCH*SEQLEN) // 8192
#define DTOFF   4224          // DINNER + CONVDIM

// ---- scratch (static device arrays; no allocation allowed) ----
__device__ float g_zx [2][MROWS][DIP];      // raw in-proj output (dir-local l)
__device__ float g_xBC[2][MROWS][CONVDIM];  // post conv + silu
__device__ float g_dt [2][MROWS][NHEADS];   // softplus(dt_raw + bias)
__device__ float g_y  [2][MROWS][DINNER];   // scan out, then normalized in-place

__device__ __forceinline__ int fliprow(int m, int flip) {
    return flip ? ((m & ~(SEQLEN - 1)) | ((SEQLEN - 1) - (m & (SEQLEN - 1)))) : m;
}

// ============================================================================
// Generic fp32 "NT" GEMM: C[m][n] = sum_k A[m][k] * W[n][k]
// A row-major MxK (row index optionally seq-flipped), W row-major NxK.
// BM=BN=128, BK=8, 256 threads, 8x8 per thread, register prefetch.
// ============================================================================
template<int N, int K>
__device__ __forceinline__ void sgemm_nt_body(
    const float* __restrict__ A, int flipA,
    const float* __restrict__ W,
    float* __restrict__ C, int accum)
{
    constexpr int BM = 128, BN = 128, BK = 8;
    __shared__ float As[BK][BM];
    __shared__ float Bs[BK][BN];

    const int tid   = threadIdx.x;
    const int mBase = blockIdx.y * BM;
    const int nBase = blockIdx.x * BN;
    const int lrow  = tid >> 1;        // 0..127
    const int lcol  = (tid & 1) * 4;   // 0 or 4

    const int am = fliprow(mBase + lrow, flipA);
    const int wn = nBase + lrow;
    const float* Aptr = A + (size_t)am * K;
    const bool wvalid = (wn < N);
    const float* Wptr = W + (size_t)wn * K;

    float4 ra = *(const float4*)(Aptr + lcol);
    float4 rw = wvalid ? *(const float4*)(Wptr + lcol) : make_float4(0.f, 0.f, 0.f, 0.f);

    const int tx = tid & 15, ty = tid >> 4;
    float acc[8][8];
    #pragma unroll
    for (int i = 0; i < 8; i++)
        #pragma unroll
        for (int j = 0; j < 8; j++) acc[i][j] = 0.f;

    for (int kt = 0; kt < K; kt += BK) {
        As[lcol + 0][lrow] = ra.x; As[lcol + 1][lrow] = ra.y;
        As[lcol + 2][lrow] = ra.z; As[lcol + 3][lrow] = ra.w;
        Bs[lcol + 0][lrow] = rw.x; Bs[lcol + 1][lrow] = rw.y;
        Bs[lcol + 2][lrow] = rw.z; Bs[lcol + 3][lrow] = rw.w;
        __syncthreads();

        if (kt + BK < K) {
            ra = *(const float4*)(Aptr + kt + BK + lcol);
            rw = wvalid ? *(const float4*)(Wptr + kt + BK + lcol)
                        : make_float4(0.f, 0.f, 0.f, 0.f);
        }

        #pragma unroll
        for (int k = 0; k < BK; k++) {
            float a[8], b[8];
            *(float4*)&a[0] = *(const float4*)&As[k][ty * 8];
            *(float4*)&a[4] = *(const float4*)&As[k][ty * 8 + 4];
            *(float4*)&b[0] = *(const float4*)&Bs[k][tx * 8];
            *(float4*)&b[4] = *(const float4*)&Bs[k][tx * 8 + 4];
            #pragma unroll
            for (int i = 0; i < 8; i++)
                #pragma unroll
                for (int j = 0; j < 8; j++)
                    acc[i][j] = fmaf(a[i], b[j], acc[i][j]);
        }
        __syncthreads();
    }

    #pragma unroll
    for (int i = 0; i < 8; i++) {
        const int m = mBase + ty * 8 + i;
        float* crow = C + (size_t)m * N;
        #pragma unroll
        for (int j = 0; j < 8; j += 4) {
            const int n = nBase + tx * 8 + j;
            if (n < N) {  // N is a multiple of 4 in all uses (4256, 1024)
                float4 v = make_float4(acc[i][j], acc[i][j+1], acc[i][j+2], acc[i][j+3]);
                if (accum) {
                    float4 o = *(const float4*)(crow + n);
                    v.x += o.x; v.y += o.y; v.z += o.z; v.w += o.w;
                }
                *(float4*)(crow + n) = v;
            }
        }
    }
}

__global__ void __launch_bounds__(256)
k_inproj(const float* __restrict__ x,
         const float* __restrict__ fw, const float* __restrict__ bw)
{
    const int dir = blockIdx.z;
    sgemm_nt_body<DIP, DMODEL>(x, dir, dir ? bw : fw, &g_zx[dir][0][0], 0);
}

__global__ void __launch_bounds__(256)
k_outproj(const float* __restrict__ w, float* __restrict__ out, int dir, int accum)
{
    sgemm_nt_body<DMODEL, DINNER>(&g_y[dir][0][0], dir, w, out, accum);
}

// ============================================================================
// Depthwise causal conv (width 4) + bias + silu, fused with dt softplus.
// ============================================================================
__global__ void __launch_bounds__(256)
k_conv(const float* __restrict__ f_cw, const float* __restrict__ f_cb,
       const float* __restrict__ f_dtb,
       const float* __restrict__ b_cw, const float* __restrict__ b_cb,
       const float* __restrict__ b_dtb)
{
    const int c   = blockIdx.x * blockDim.x + threadIdx.x;
    const int m   = blockIdx.y;
    const int dir = blockIdx.z;
    const int l   = m & (SEQLEN - 1);

    if (c < CONVDIM) {
        const float* cw = dir ? b_cw : f_cw;
        const float* cb = dir ? b_cb : f_cb;
        float acc = cb[c];
        #pragma unroll
        for (int j = 0; j < 4; j++) {
            const int ls = l - 3 + j;
            if (ls >= 0)
                acc = fmaf(cw[c * 4 + j], g_zx[dir][m - 3 + j][DINNER + c], acc);
        }
        // silu
        g_xBC[dir][m][c] = acc / (1.f + expf(-acc));
    } else if (c < CONVDIM + NHEADS) {
        const int h = c - CONVDIM;
        const float* dtb = dir ? b_dtb : f_dtb;
        const float v = g_zx[dir][m][DTOFF + h] + dtb[h];
        g_dt[dir][m][h] = (v > 20.f) ? v : log1pf(expf(v));
    }
}

// ============================================================================
// SSD scan: one CTA per (dir, batch, head); 64 threads, each thread owns one
// headdim row p with the full 64-wide state in registers.
// ============================================================================
__global__ void __launch_bounds__(64)
k_scan(const float* __restrict__ fA, const float* __restrict__ fD,
       const float* __restrict__ bA, const float* __restrict__ bD)
{
    const int h = blockIdx.x, b = blockIdx.y, dir = blockIdx.z;
    const int p = threadIdx.x;
    const float Ah = -expf((dir ? bA : fA)[h]);
    const float Dh = (dir ? bD : fD)[h];

    __shared__ float Bs[DSTATE], Cs[DSTATE];
    float S[DSTATE];
    #pragma unroll
    for (int n = 0; n < DSTATE; n++) S[n] = 0.f;

    const int mBase = b * SEQLEN;
    for (int l = 0; l < SEQLEN; l++) {
        const float* row = &g_xBC[dir][mBase + l][0];
        Bs[p] = row[DINNER + p];
        Cs[p] = row[DINNER + DSTATE + p];
        const float xp = row[h * HEADDIM + p];
        const float dt = g_dt[dir][mBase + l][h];
        __syncthreads();

        const float dA = expf(dt * Ah);
        const float cf = dt * xp;
        float y0 = 0.f, y1 = 0.f, y2 = 0.f, y3 = 0.f;
        #pragma unroll
        for (int n4 = 0; n4 < DSTATE / 4; n4++) {
            const float4 b4 = *(const float4*)&Bs[n4 * 4];
            const float4 c4 = *(const float4*)&Cs[n4 * 4];
            S[n4*4+0] = fmaf(cf, b4.x, S[n4*4+0] * dA); y0 = fmaf(S[n4*4+0], c4.x, y0);
            S[n4*4+1] = fmaf(cf, b4.y, S[n4*4+1] * dA); y1 = fmaf(S[n4*4+1], c4.y, y1);
            S[n4*4+2] = fmaf(cf, b4.z, S[n4*4+2] * dA); y2 = fmaf(S[n4*4+2], c4.z, y2);
            S[n4*4+3] = fmaf(cf, b4.w, S[n4*4+3] * dA); y3 = fmaf(S[n4*4+3], c4.w, y3);
        }
        g_y[dir][mBase + l][h * HEADDIM + p] = (y0 + y1) + (y2 + y3) + Dh * xp;
        __syncthreads();
    }
}

// ============================================================================
// Gate with silu(z), RMSNorm over DINNER, scale by norm_w. In-place on g_y.
// ============================================================================
__global__ void __launch_bounds__(256)
k_gate(const float* __restrict__ fnw, const float* __restrict__ bnw)
{
    const int m = blockIdx.x, dir = blockIdx.y;
    const int tid = threadIdx.x;  // 256
    const float* nw = dir ? bnw : fnw;

    float v[8];
    float ss = 0.f;
    #pragma unroll
    for (int i = 0; i < 8; i++) {
        const int d = tid + i * 256;
        const float y = g_y[dir][m][d];
        const float z = g_zx[dir][m][d];
        const float val = y * (z / (1.f + expf(-z)));
        v[i] = val;
        ss = fmaf(val, val, ss);
    }
    __shared__ float red[8];
    #pragma unroll
    for (int o = 16; o > 0; o >>= 1) ss += __shfl_xor_sync(0xffffffffu, ss, o);
    if ((tid & 31) == 0) red[tid >> 5] = ss;
    __syncthreads();
    if (tid < 8) {
        float t = red[tid];
        #pragma unroll
        for (int o = 4; o > 0; o >>= 1) t += __shfl_xor_sync(0xffu, t, o);
        if (tid == 0) red[0] = t;
    }
    __syncthreads();
    const float scale = rsqrtf(red[0] / (float)DINNER + 1e-5f);
    #pragma unroll
    for (int i = 0; i < 8; i++) {
        const int d = tid + i * 256;
        g_y[dir][m][d] = v[i] * scale * nw[d];
    }
}

// ============================================================================
extern "C" void kernel_launch(void* const* d_in, const int* in_sizes, int n_in,
                              void* d_out, int out_size)
{
    (void)in_sizes; (void)n_in; (void)out_size;
    const float* x      = (const float*)d_in[0];
    const float* f_in_w = (const float*)d_in[1];
    const float* f_cw   = (const float*)d_in[2];
    const float* f_cb   = (const float*)d_in[3];
    const float* f_dtb  = (const float*)d_in[4];
    const float* f_Al   = (const float*)d_in[5];
    const float* f_Dp   = (const float*)d_in[6];
    const float* f_nw   = (const float*)d_in[7];
    const float* f_ow   = (const float*)d_in[8];
    const float* b_in_w = (const float*)d_in[9];
    const float* b_cw   = (const float*)d_in[10];
    const float* b_cb   = (const float*)d_in[11];
    const float* b_dtb  = (const float*)d_in[12];
    const float* b_Al   = (const float*)d_in[13];
    const float* b_Dp   = (const float*)d_in[14];
    const float* b_nw   = (const float*)d_in[15];
    const float* b_ow   = (const float*)d_in[16];
    float* out = (float*)d_out;

    dim3 gIn((DIP + 127) / 128, MROWS / 128, 2);          // 34 x 64 x 2
    k_inproj<<<gIn, 256>>>(x, f_in_w, b_in_w);

    dim3 gConv((CONVDIM + NHEADS + 255) / 256, MROWS, 2); // 9 x 8192 x 2
    k_conv<<<gConv, 256>>>(f_cw, f_cb, f_dtb, b_cw, b_cb, b_dtb);

    k_scan<<<dim3(NHEADS, BATCH, 2), HEADDIM>>>(f_Al, f_Dp, b_Al, b_Dp);

    k_gate<<<dim3(MROWS, 2), 256>>>(f_nw, b_nw);

    dim3 gOut(DMODEL / 128, MROWS / 128);                 // 8 x 64
    k_outproj<<<gOut, 256>>>(f_ow, out, 0, 0);
    k_outproj<<<gOut, 256>>>(b_ow, out, 1, 1);
}

// round 4
// speedup vs baseline: 2.0069x; 2.0069x over previous
#include <cuda_runtime.h>
#include <math.h>
#include <stdint.h>

#define BATCH   4
#define SEQLEN  2048
#define DMODEL  1024
#define DINNER  2048
#define DSTATE  64
#define NHEADS  32
#define HEADDIM 64
#define CONVDIM 2176          // DINNER + 2*DSTATE
#define DIP     4256          // 2*DINNER + 2*DSTATE + NHEADS
#define MROWS   (BATCH*SEQLEN) // 8192
#define DTOFF   4224          // DINNER + CONVDIM

// ---- scratch (static device arrays; no allocation allowed) ----
__device__ float g_zx [2][MROWS][DIP];      // raw in-proj output (dir-local l)
__device__ float g_xBC[2][MROWS][CONVDIM];  // post conv + silu
__device__ float g_dt [2][MROWS][NHEADS];   // softplus(dt_raw + bias)
__device__ float g_y  [2][MROWS][DINNER];   // scan out, then normalized in-place

__device__ __forceinline__ int fliprow(int m, int flip) {
    return flip ? ((m & ~(SEQLEN - 1)) | ((SEQLEN - 1) - (m & (SEQLEN - 1)))) : m;
}

// ============================================================================
// tf32 tensor-core GEMM (mma.sync.m16n8k8): C[m][n] (+)= sum_k A[m][k]*W[n][k]
// A row-major MxK (rows optionally seq-flipped), W row-major NxK.
// BM=BN=128, BK=16, 256 thr = 8 warps (2x4), warp tile 64x32.
// Double-buffered cp.async smem, pitch 20 (bank-conflict-free frag loads).
// ============================================================================
#define SPITCH 20   // 16 + 4 pad floats

__device__ __forceinline__ void cp_async16(float* smem_dst, const float* gmem_src, int src_bytes) {
    uint32_t s = (uint32_t)__cvta_generic_to_shared(smem_dst);
    asm volatile("cp.async.cg.shared.global [%0], [%1], 16, %2;\n"
                 :: "r"(s), "l"(gmem_src), "r"(src_bytes));
}
__device__ __forceinline__ void cp_commit() { asm volatile("cp.async.commit_group;\n"); }
__device__ __forceinline__ void cp_wait0()  { asm volatile("cp.async.wait_group 0;\n"); }

__device__ __forceinline__ uint32_t f2tf32(float x) {
    uint32_t u;
    asm("cvt.rna.tf32.f32 %0, %1;" : "=r"(u) : "f"(x));
    return u;
}

__device__ __forceinline__ void mma_16n8k8(float c[4], const uint32_t a[4], const uint32_t b[2]) {
    asm volatile("mma.sync.aligned.m16n8k8.row.col.f32.tf32.tf32.f32 "
                 "{%0,%1,%2,%3}, {%4,%5,%6,%7}, {%8,%9}, {%0,%1,%2,%3};"
                 : "+f"(c[0]), "+f"(c[1]), "+f"(c[2]), "+f"(c[3])
                 : "r"(a[0]), "r"(a[1]), "r"(a[2]), "r"(a[3]), "r"(b[0]), "r"(b[1]));
}

template<int N, int K>
__device__ __forceinline__ void tgemm_nt_body(
    const float* __restrict__ A, int flipA,
    const float* __restrict__ W,
    float* __restrict__ C, int accum)
{
    __shared__ float As[2][128][SPITCH];
    __shared__ float Bs[2][128][SPITCH];

    const int tid   = threadIdx.x;
    const int mBase = blockIdx.y * 128;
    const int nBase = blockIdx.x * 128;

    // global->smem load mapping: 512 16B chunks per tile; thread does chunks tid, tid+256
    const int r0 = tid >> 2;              // 0..63
    const int kc = (tid & 3) * 4;         // 0,4,8,12

    const int amr0 = fliprow(mBase + r0, flipA);
    const int amr1 = fliprow(mBase + r0 + 64, flipA);
    const float* Ar0 = A + (size_t)amr0 * K + kc;
    const float* Ar1 = A + (size_t)amr1 * K + kc;
    const int wn0 = nBase + r0, wn1 = nBase + r0 + 64;
    const float* Wr0 = W + (size_t)wn0 * K + kc;
    const float* Wr1 = W + (size_t)wn1 * K + kc;
    const int wb0 = (wn0 < N) ? 16 : 0;
    const int wb1 = (wn1 < N) ? 16 : 0;

    const int lane = tid & 31;
    const int g    = lane >> 2;   // 0..7
    const int tig  = lane & 3;    // 0..3
    const int warp = tid >> 5;
    const int wm   = (warp & 1) * 64;
    const int wn   = (warp >> 1) * 32;

    float acc[4][4][4];
    #pragma unroll
    for (int mt = 0; mt < 4; mt++)
        #pragma unroll
        for (int nt = 0; nt < 4; nt++)
            #pragma unroll
            for (int c = 0; c < 4; c++) acc[mt][nt][c] = 0.f;

    // prologue: stage 0
    cp_async16(&As[0][r0][kc],      Ar0, 16);
    cp_async16(&As[0][r0 + 64][kc], Ar1, 16);
    cp_async16(&Bs[0][r0][kc],      Wr0, wb0);
    cp_async16(&Bs[0][r0 + 64][kc], Wr1, wb1);
    cp_commit();

    constexpr int NT = K / 16;
    #pragma unroll 1
    for (int kt = 0; kt < NT; kt++) {
        cp_wait0();
        __syncthreads();

        if (kt + 1 < NT) {
            const int st = (kt + 1) & 1;
            const int ko = (kt + 1) * 16;
            cp_async16(&As[st][r0][kc],      Ar0 + ko, 16);
            cp_async16(&As[st][r0 + 64][kc], Ar1 + ko, 16);
            cp_async16(&Bs[st][r0][kc],      Wr0 + ko, wb0);
            cp_async16(&Bs[st][r0 + 64][kc], Wr1 + ko, wb1);
            cp_commit();
        }

        const int st = kt & 1;
        #pragma unroll
        for (int kk = 0; kk < 16; kk += 8) {
            uint32_t af[4][4], bf[4][2];
            #pragma unroll
            for (int mt = 0; mt < 4; mt++) {
                const int m0 = wm + mt * 16 + g;
                af[mt][0] = f2tf32(As[st][m0][kk + tig]);
                af[mt][1] = f2tf32(As[st][m0 + 8][kk + tig]);
                af[mt][2] = f2tf32(As[st][m0][kk + tig + 4]);
                af[mt][3] = f2tf32(As[st][m0 + 8][kk + tig + 4]);
            }
            #pragma unroll
            for (int nt = 0; nt < 4; nt++) {
                const int n0 = wn + nt * 8 + g;
                bf[nt][0] = f2tf32(Bs[st][n0][kk + tig]);
                bf[nt][1] = f2tf32(Bs[st][n0][kk + tig + 4]);
            }
            #pragma unroll
            for (int mt = 0; mt < 4; mt++)
                #pragma unroll
                for (int nt = 0; nt < 4; nt++)
                    mma_16n8k8(acc[mt][nt], af[mt], bf[nt]);
        }
        __syncthreads();
    }

    // epilogue
    #pragma unroll
    for (int mt = 0; mt < 4; mt++) {
        const int m0 = mBase + wm + mt * 16 + g;
        float* crow0 = C + (size_t)m0 * N;
        float* crow1 = C + (size_t)(m0 + 8) * N;
        #pragma unroll
        for (int nt = 0; nt < 4; nt++) {
            const int n = nBase + wn + nt * 8 + tig * 2;
            if (n < N) {
                float2 v0 = make_float2(acc[mt][nt][0], acc[mt][nt][1]);
                float2 v1 = make_float2(acc[mt][nt][2], acc[mt][nt][3]);
                if (accum) {
                    float2 o0 = *(const float2*)(crow0 + n);
                    float2 o1 = *(const float2*)(crow1 + n);
                    v0.x += o0.x; v0.y += o0.y; v1.x += o1.x; v1.y += o1.y;
                }
                *(float2*)(crow0 + n) = v0;
                *(float2*)(crow1 + n) = v1;
            }
        }
    }
}

__global__ void __launch_bounds__(256)
k_inproj(const float* __restrict__ x,
         const float* __restrict__ fw, const float* __restrict__ bw)
{
    const int dir = blockIdx.z;
    tgemm_nt_body<DIP, DMODEL>(x, dir, dir ? bw : fw, &g_zx[dir][0][0], 0);
}

__global__ void __launch_bounds__(256)
k_outproj(const float* __restrict__ w, float* __restrict__ out, int dir, int accum)
{
    tgemm_nt_body<DMODEL, DINNER>(&g_y[dir][0][0], dir, w, out, accum);
}

// ============================================================================
// Depthwise causal conv (width 4) + bias + silu, fused with dt softplus.
// ============================================================================
__global__ void __launch_bounds__(256)
k_conv(const float* __restrict__ f_cw, const float* __restrict__ f_cb,
       const float* __restrict__ f_dtb,
       const float* __restrict__ b_cw, const float* __restrict__ b_cb,
       const float* __restrict__ b_dtb)
{
    const int c   = blockIdx.x * blockDim.x + threadIdx.x;
    const int m   = blockIdx.y;
    const int dir = blockIdx.z;
    const int l   = m & (SEQLEN - 1);

    if (c < CONVDIM) {
        const float* cw = dir ? b_cw : f_cw;
        const float* cb = dir ? b_cb : f_cb;
        float acc = cb[c];
        #pragma unroll
        for (int j = 0; j < 4; j++) {
            const int ls = l - 3 + j;
            if (ls >= 0)
                acc = fmaf(cw[c * 4 + j], g_zx[dir][m - 3 + j][DINNER + c], acc);
        }
        g_xBC[dir][m][c] = acc / (1.f + expf(-acc));
    } else if (c < CONVDIM + NHEADS) {
        const int h = c - CONVDIM;
        const float* dtb = dir ? b_dtb : f_dtb;
        const float v = g_zx[dir][m][DTOFF + h] + dtb[h];
        g_dt[dir][m][h] = (v > 20.f) ? v : log1pf(expf(v));
    }
}

// ============================================================================
// SSD scan: one CTA per (dir, batch, head); 64 threads, each thread owns one
// headdim row p with the full 64-wide state in registers.
// ============================================================================
__global__ void __launch_bounds__(64)
k_scan(const float* __restrict__ fA, const float* __restrict__ fD,
       const float* __restrict__ bA, const float* __restrict__ bD)
{
    const int h = blockIdx.x, b = blockIdx.y, dir = blockIdx.z;
    const int p = threadIdx.x;
    const float Ah = -expf((dir ? bA : fA)[h]);
    const float Dh = (dir ? bD : fD)[h];

    __shared__ float Bs[DSTATE], Cs[DSTATE];
    float S[DSTATE];
    #pragma unroll
    for (int n = 0; n < DSTATE; n++) S[n] = 0.f;

    const int mBase = b * SEQLEN;
    for (int l = 0; l < SEQLEN; l++) {
        const float* row = &g_xBC[dir][mBase + l][0];
        Bs[p] = row[DINNER + p];
        Cs[p] = row[DINNER + DSTATE + p];
        const float xp = row[h * HEADDIM + p];
        const float dt = g_dt[dir][mBase + l][h];
        __syncthreads();

        const float dA = expf(dt * Ah);
        const float cf = dt * xp;
        float y0 = 0.f, y1 = 0.f, y2 = 0.f, y3 = 0.f;
        #pragma unroll
        for (int n4 = 0; n4 < DSTATE / 4; n4++) {
            const float4 b4 = *(const float4*)&Bs[n4 * 4];
            const float4 c4 = *(const float4*)&Cs[n4 * 4];
            S[n4*4+0] = fmaf(cf, b4.x, S[n4*4+0] * dA); y0 = fmaf(S[n4*4+0], c4.x, y0);
            S[n4*4+1] = fmaf(cf, b4.y, S[n4*4+1] * dA); y1 = fmaf(S[n4*4+1], c4.y, y1);
            S[n4*4+2] = fmaf(cf, b4.z, S[n4*4+2] * dA); y2 = fmaf(S[n4*4+2], c4.z, y2);
            S[n4*4+3] = fmaf(cf, b4.w, S[n4*4+3] * dA); y3 = fmaf(S[n4*4+3], c4.w, y3);
        }
        g_y[dir][mBase + l][h * HEADDIM + p] = (y0 + y1) + (y2 + y3) + Dh * xp;
        __syncthreads();
    }
}

// ============================================================================
// Gate with silu(z), RMSNorm over DINNER, scale by norm_w. In-place on g_y.
// ============================================================================
__global__ void __launch_bounds__(256)
k_gate(const float* __restrict__ fnw, const float* __restrict__ bnw)
{
    const int m = blockIdx.x, dir = blockIdx.y;
    const int tid = threadIdx.x;  // 256
    const float* nw = dir ? bnw : fnw;

    float v[8];
    float ss = 0.f;
    #pragma unroll
    for (int i = 0; i < 8; i++) {
        const int d = tid + i * 256;
        const float y = g_y[dir][m][d];
        const float z = g_zx[dir][m][d];
        const float val = y * (z / (1.f + expf(-z)));
        v[i] = val;
        ss = fmaf(val, val, ss);
    }
    __shared__ float red[8];
    #pragma unroll
    for (int o = 16; o > 0; o >>= 1) ss += __shfl_xor_sync(0xffffffffu, ss, o);
    if ((tid & 31) == 0) red[tid >> 5] = ss;
    __syncthreads();
    if (tid < 8) {
        float t = red[tid];
        #pragma unroll
        for (int o = 4; o > 0; o >>= 1) t += __shfl_xor_sync(0xffu, t, o);
        if (tid == 0) red[0] = t;
    }
    __syncthreads();
    const float scale = rsqrtf(red[0] / (float)DINNER + 1e-5f);
    #pragma unroll
    for (int i = 0; i < 8; i++) {
        const int d = tid + i * 256;
        g_y[dir][m][d] = v[i] * scale * nw[d];
    }
}

// ============================================================================
extern "C" void kernel_launch(void* const* d_in, const int* in_sizes, int n_in,
                              void* d_out, int out_size)
{
    (void)in_sizes; (void)n_in; (void)out_size;
    const float* x      = (const float*)d_in[0];
    const float* f_in_w = (const float*)d_in[1];
    const float* f_cw   = (const float*)d_in[2];
    const float* f_cb   = (const float*)d_in[3];
    const float* f_dtb  = (const float*)d_in[4];
    const float* f_Al   = (const float*)d_in[5];
    const float* f_Dp   = (const float*)d_in[6];
    const float* f_nw   = (const float*)d_in[7];
    const float* f_ow   = (const float*)d_in[8];
    const float* b_in_w = (const float*)d_in[9];
    const float* b_cw   = (const float*)d_in[10];
    const float* b_cb   = (const float*)d_in[11];
    const float* b_dtb  = (const float*)d_in[12];
    const float* b_Al   = (const float*)d_in[13];
    const float* b_Dp   = (const float*)d_in[14];
    const float* b_nw   = (const float*)d_in[15];
    const float* b_ow   = (const float*)d_in[16];
    float* out = (float*)d_out;

    dim3 gIn((DIP + 127) / 128, MROWS / 128, 2);          // 34 x 64 x 2
    k_inproj<<<gIn, 256>>>(x, f_in_w, b_in_w);

    dim3 gConv((CONVDIM + NHEADS + 255) / 256, MROWS, 2); // 9 x 8192 x 2
    k_conv<<<gConv, 256>>>(f_cw, f_cb, f_dtb, b_cw, b_cb, b_dtb);

    k_scan<<<dim3(NHEADS, BATCH, 2), HEADDIM>>>(f_Al, f_Dp, b_Al, b_Dp);

    k_gate<<<dim3(MROWS, 2), 256>>>(f_nw, b_nw);

    dim3 gOut(DMODEL / 128, MROWS / 128);                 // 8 x 64
    k_outproj<<<gOut, 256>>>(f_ow, out, 0, 0);
    k_outproj<<<gOut, 256>>>(b_ow, out, 1, 1);
}

// round 6
// speedup vs baseline: 2.0661x; 1.0295x over previous
#include <cuda_runtime.h>
#include <math.h>
#include <stdint.h>

#define BATCH   4
#define SEQLEN  2048
#define DMODEL  1024
#define DINNER  2048
#define DSTATE  64
#define NHEADS  32
#define HEADDIM 64
#define CONVDIM 2176          // DINNER + 2*DSTATE
#define DIP     4256          // 2*DINNER + 2*DSTATE + NHEADS
#define MROWS   (BATCH*SEQLEN) // 8192
#define DTOFF   4224          // DINNER + CONVDIM

// ---- scratch (static device arrays; identical footprint to the passing R4 build) ----
__device__ float g_zx [2][MROWS][DIP];      // raw in-proj output
__device__ float g_xBC[2][MROWS][CONVDIM];  // ALIAS: tf32 in-proj weights (before conv),
                                            //        tf32 out-proj weights (after scan);
                                            // then post-conv+silu activations
__device__ float g_dt [2][MROWS][NHEADS];   // softplus(dt_raw + bias)
__device__ float g_y  [2][MROWS][DINNER];   // ALIAS: tf32-rounded x (before scan);
                                            // then scan out -> gated/normed (tf32-rounded)

__device__ __forceinline__ int fliprow(int m, int flip) {
    return flip ? ((m & ~(SEQLEN - 1)) | ((SEQLEN - 1) - (m & (SEQLEN - 1)))) : m;
}

__device__ __forceinline__ uint32_t f2tf32(float x) {
    uint32_t u;
    asm("cvt.rna.tf32.f32 %0, %1;" : "=r"(u) : "f"(x));
    return u;
}

// ============================================================================
// Pre-round fp32 -> tf32-precision fp32 into aliased scratch regions.
// dst selector: 0 = xr (g_y base), 1/2 = in-proj W dir0/1 (g_xBC base),
//               3/4 = out-proj W dir0/1 (g_xBC base).
// ============================================================================
__global__ void __launch_bounds__(256)
k_round(const float* __restrict__ src, int which, int n4)
{
    float* dst;
    switch (which) {
        case 0:  dst = &g_y[0][0][0]; break;
        case 1:  dst = &g_xBC[0][0][0]; break;
        case 2:  dst = &g_xBC[0][0][0] + (size_t)DIP * DMODEL; break;
        case 3:  dst = &g_xBC[0][0][0]; break;
        default: dst = &g_xBC[0][0][0] + (size_t)DMODEL * DINNER; break;
    }
    const int i = blockIdx.x * blockDim.x + threadIdx.x;
    if (i < n4) {
        float4 v = ((const float4*)src)[i];
        v.x = __uint_as_float(f2tf32(v.x));
        v.y = __uint_as_float(f2tf32(v.y));
        v.z = __uint_as_float(f2tf32(v.z));
        v.w = __uint_as_float(f2tf32(v.w));
        ((float4*)dst)[i] = v;
    }
}

// ============================================================================
// tf32 tensor-core GEMM (mma.sync.m16n8k8): C[m][n] (+)= sum_k A[m][k]*W[n][k]
// Inputs are PRE-ROUNDED to tf32 precision -> mainloop has zero converts.
// BM=BN=128, BK=16, 256 thr = 8 warps (2x4), warp tile 64x32.
// Double-buffered cp.async smem, pitch 20 (bank-conflict-free frag loads).
// ============================================================================
#define SPITCH 20   // 16 + 4 pad floats

__device__ __forceinline__ void cp_async16(float* smem_dst, const float* gmem_src, int src_bytes) {
    uint32_t s = (uint32_t)__cvta_generic_to_shared(smem_dst);
    asm volatile("cp.async.cg.shared.global [%0], [%1], 16, %2;\n"
                 :: "r"(s), "l"(gmem_src), "r"(src_bytes));
}
__device__ __forceinline__ void cp_commit() { asm volatile("cp.async.commit_group;\n"); }
__device__ __forceinline__ void cp_wait0()  { asm volatile("cp.async.wait_group 0;\n"); }

__device__ __forceinline__ void mma_16n8k8(float c[4], const uint32_t a[4], const uint32_t b[2]) {
    asm volatile("mma.sync.aligned.m16n8k8.row.col.f32.tf32.tf32.f32 "
                 "{%0,%1,%2,%3}, {%4,%5,%6,%7}, {%8,%9}, {%0,%1,%2,%3};"
                 : "+f"(c[0]), "+f"(c[1]), "+f"(c[2]), "+f"(c[3])
                 : "r"(a[0]), "r"(a[1]), "r"(a[2]), "r"(a[3]), "r"(b[0]), "r"(b[1]));
}

template<int N, int K>
__device__ __forceinline__ void tgemm_nt_body(
    const float* __restrict__ A, int flipA,
    const float* __restrict__ W,
    float* __restrict__ C, int accum)
{
    __shared__ float As[2][128][SPITCH];
    __shared__ float Bs[2][128][SPITCH];

    const int tid   = threadIdx.x;
    const int mBase = blockIdx.y * 128;
    const int nBase = blockIdx.x * 128;

    const int r0 = tid >> 2;              // 0..63
    const int kc = (tid & 3) * 4;         // 0,4,8,12

    const int amr0 = fliprow(mBase + r0, flipA);
    const int amr1 = fliprow(mBase + r0 + 64, flipA);
    const float* Ar0 = A + (size_t)amr0 * K + kc;
    const float* Ar1 = A + (size_t)amr1 * K + kc;
    const int wn0 = nBase + r0, wn1 = nBase + r0 + 64;
    const float* Wr0 = W + (size_t)wn0 * K + kc;
    const float* Wr1 = W + (size_t)wn1 * K + kc;
    const int wb0 = (wn0 < N) ? 16 : 0;
    const int wb1 = (wn1 < N) ? 16 : 0;

    const int lane = tid & 31;
    const int g    = lane >> 2;   // 0..7
    const int tig  = lane & 3;    // 0..3
    const int warp = tid >> 5;
    const int wm   = (warp & 1) * 64;
    const int wn   = (warp >> 1) * 32;

    float acc[4][4][4];
    #pragma unroll
    for (int mt = 0; mt < 4; mt++)
        #pragma unroll
        for (int nt = 0; nt < 4; nt++)
            #pragma unroll
            for (int c = 0; c < 4; c++) acc[mt][nt][c] = 0.f;

    cp_async16(&As[0][r0][kc],      Ar0, 16);
    cp_async16(&As[0][r0 + 64][kc], Ar1, 16);
    cp_async16(&Bs[0][r0][kc],      Wr0, wb0);
    cp_async16(&Bs[0][r0 + 64][kc], Wr1, wb1);
    cp_commit();

    constexpr int NT = K / 16;
    #pragma unroll 1
    for (int kt = 0; kt < NT; kt++) {
        cp_wait0();
        __syncthreads();

        if (kt + 1 < NT) {
            const int st = (kt + 1) & 1;
            const int ko = (kt + 1) * 16;
            cp_async16(&As[st][r0][kc],      Ar0 + ko, 16);
            cp_async16(&As[st][r0 + 64][kc], Ar1 + ko, 16);
            cp_async16(&Bs[st][r0][kc],      Wr0 + ko, wb0);
            cp_async16(&Bs[st][r0 + 64][kc], Wr1 + ko, wb1);
            cp_commit();
        }

        const int st = kt & 1;
        #pragma unroll
        for (int kk = 0; kk < 16; kk += 8) {
            uint32_t af[4][4], bf[4][2];
            #pragma unroll
            for (int mt = 0; mt < 4; mt++) {
                const int m0 = wm + mt * 16 + g;
                af[mt][0] = __float_as_uint(As[st][m0][kk + tig]);
                af[mt][1] = __float_as_uint(As[st][m0 + 8][kk + tig]);
                af[mt][2] = __float_as_uint(As[st][m0][kk + tig + 4]);
                af[mt][3] = __float_as_uint(As[st][m0 + 8][kk + tig + 4]);
            }
            #pragma unroll
            for (int nt = 0; nt < 4; nt++) {
                const int n0 = wn + nt * 8 + g;
                bf[nt][0] = __float_as_uint(Bs[st][n0][kk + tig]);
                bf[nt][1] = __float_as_uint(Bs[st][n0][kk + tig + 4]);
            }
            #pragma unroll
            for (int mt = 0; mt < 4; mt++)
                #pragma unroll
                for (int nt = 0; nt < 4; nt++)
                    mma_16n8k8(acc[mt][nt], af[mt], bf[nt]);
        }
        __syncthreads();
    }

    // epilogue
    #pragma unroll
    for (int mt = 0; mt < 4; mt++) {
        const int m0 = mBase + wm + mt * 16 + g;
        float* crow0 = C + (size_t)m0 * N;
        float* crow1 = C + (size_t)(m0 + 8) * N;
        #pragma unroll
        for (int nt = 0; nt < 4; nt++) {
            const int n = nBase + wn + nt * 8 + tig * 2;
            if (n < N) {
                float2 v0 = make_float2(acc[mt][nt][0], acc[mt][nt][1]);
                float2 v1 = make_float2(acc[mt][nt][2], acc[mt][nt][3]);
                if (accum) {
                    float2 o0 = *(const float2*)(crow0 + n);
                    float2 o1 = *(const float2*)(crow1 + n);
                    v0.x += o0.x; v0.y += o0.y; v1.x += o1.x; v1.y += o1.y;
                }
                *(float2*)(crow0 + n) = v0;
                *(float2*)(crow1 + n) = v1;
            }
        }
    }
}

__global__ void __launch_bounds__(256)
k_inproj()
{
    const int dir = blockIdx.z;
    const float* xr  = &g_y[0][0][0];                                   // rounded x
    const float* win = &g_xBC[0][0][0] + (size_t)dir * DIP * DMODEL;    // rounded W_in
    tgemm_nt_body<DIP, DMODEL>(xr, dir, win, &g_zx[dir][0][0], 0);
}

__global__ void __launch_bounds__(256)
k_outproj(float* __restrict__ out, int dir, int accum)
{
    const float* wout = &g_xBC[0][0][0] + (size_t)dir * DMODEL * DINNER; // rounded W_out
    tgemm_nt_body<DMODEL, DINNER>(&g_y[dir][0][0], dir, wout, out, accum);
}

// ============================================================================
// Depthwise causal conv (width 4) + bias + silu, fused with dt softplus.
// ============================================================================
__global__ void __launch_bounds__(256)
k_conv(const float* __restrict__ f_cw, const float* __restrict__ f_cb,
       const float* __restrict__ f_dtb,
       const float* __restrict__ b_cw, const float* __restrict__ b_cb,
       const float* __restrict__ b_dtb)
{
    const int c   = blockIdx.x * blockDim.x + threadIdx.x;
    const int m   = blockIdx.y;
    const int dir = blockIdx.z;
    const int l   = m & (SEQLEN - 1);

    if (c < CONVDIM) {
        const float* cw = dir ? b_cw : f_cw;
        const float* cb = dir ? b_cb : f_cb;
        float acc = cb[c];
        #pragma unroll
        for (int j = 0; j < 4; j++) {
            const int ls = l - 3 + j;
            if (ls >= 0)
                acc = fmaf(cw[c * 4 + j], g_zx[dir][m - 3 + j][DINNER + c], acc);
        }
        g_xBC[dir][m][c] = acc / (1.f + expf(-acc));
    } else if (c < CONVDIM + NHEADS) {
        const int h = c - CONVDIM;
        const float* dtb = dir ? b_dtb : f_dtb;
        const float v = g_zx[dir][m][DTOFF + h] + dtb[h];
        g_dt[dir][m][h] = (v > 20.f) ? v : log1pf(expf(v));
    }
}

// ============================================================================
// SSD scan: one CTA per (dir, batch, head); 64 threads, each thread owns one
// headdim row p with the full 64-wide state in registers.
// ============================================================================
__global__ void __launch_bounds__(64)
k_scan(const float* __restrict__ fA, const float* __restrict__ fD,
       const float* __restrict__ bA, const float* __restrict__ bD)
{
    const int h = blockIdx.x, b = blockIdx.y, dir = blockIdx.z;
    const int p = threadIdx.x;
    const float Ah = -expf((dir ? bA : fA)[h]);
    const float Dh = (dir ? bD : fD)[h];

    __shared__ float Bs[DSTATE], Cs[DSTATE];
    float S[DSTATE];
    #pragma unroll
    for (int n = 0; n < DSTATE; n++) S[n] = 0.f;

    const int mBase = b * SEQLEN;
    for (int l = 0; l < SEQLEN; l++) {
        const float* row = &g_xBC[dir][mBase + l][0];
        Bs[p] = row[DINNER + p];
        Cs[p] = row[DINNER + DSTATE + p];
        const float xp = row[h * HEADDIM + p];
        const float dt = g_dt[dir][mBase + l][h];
        __syncthreads();

        const float dA = expf(dt * Ah);
        const float cf = dt * xp;
        float y0 = 0.f, y1 = 0.f, y2 = 0.f, y3 = 0.f;
        #pragma unroll
        for (int n4 = 0; n4 < DSTATE / 4; n4++) {
            const float4 b4 = *(const float4*)&Bs[n4 * 4];
            const float4 c4 = *(const float4*)&Cs[n4 * 4];
            S[n4*4+0] = fmaf(cf, b4.x, S[n4*4+0] * dA); y0 = fmaf(S[n4*4+0], c4.x, y0);
            S[n4*4+1] = fmaf(cf, b4.y, S[n4*4+1] * dA); y1 = fmaf(S[n4*4+1], c4.y, y1);
            S[n4*4+2] = fmaf(cf, b4.z, S[n4*4+2] * dA); y2 = fmaf(S[n4*4+2], c4.z, y2);
            S[n4*4+3] = fmaf(cf, b4.w, S[n4*4+3] * dA); y3 = fmaf(S[n4*4+3], c4.w, y3);
        }
        g_y[dir][mBase + l][h * HEADDIM + p] = (y0 + y1) + (y2 + y3) + Dh * xp;
        __syncthreads();
    }
}

// ============================================================================
// Gate with silu(z), RMSNorm over DINNER, scale by norm_w. In-place on g_y.
// Output pre-rounded to tf32 precision (it feeds the out-proj MMA directly).
// ============================================================================
__global__ void __launch_bounds__(256)
k_gate(const float* __restrict__ fnw, const float* __restrict__ bnw)
{
    const int m = blockIdx.x, dir = blockIdx.y;
    const int tid = threadIdx.x;  // 256
    const float* nw = dir ? bnw : fnw;

    float v[8];
    float ss = 0.f;
    #pragma unroll
    for (int i = 0; i < 8; i++) {
        const int d = tid + i * 256;
        const float y = g_y[dir][m][d];
        const float z = g_zx[dir][m][d];
        const float val = y * (z / (1.f + expf(-z)));
        v[i] = val;
        ss = fmaf(val, val, ss);
    }
    __shared__ float red[8];
    #pragma unroll
    for (int o = 16; o > 0; o >>= 1) ss += __shfl_xor_sync(0xffffffffu, ss, o);
    if ((tid & 31) == 0) red[tid >> 5] = ss;
    __syncthreads();
    if (tid < 8) {
        float t = red[tid];
        #pragma unroll
        for (int o = 4; o > 0; o >>= 1) t += __shfl_xor_sync(0xffu, t, o);
        if (tid == 0) red[0] = t;
    }
    __syncthreads();
    const float scale = rsqrtf(red[0] / (float)DINNER + 1e-5f);
    #pragma unroll
    for (int i = 0; i < 8; i++) {
        const int d = tid + i * 256;
        g_y[dir][m][d] = __uint_as_float(f2tf32(v[i] * scale * nw[d]));
    }
}

// ============================================================================
extern "C" void kernel_launch(void* const* d_in, const int* in_sizes, int n_in,
                              void* d_out, int out_size)
{
    (void)in_sizes; (void)n_in; (void)out_size;
    const float* x      = (const float*)d_in[0];
    const float* f_in_w = (const float*)d_in[1];
    const float* f_cw   = (const float*)d_in[2];
    const float* f_cb   = (const float*)d_in[3];
    const float* f_dtb  = (const float*)d_in[4];
    const float* f_Al   = (const float*)d_in[5];
    const float* f_Dp   = (const float*)d_in[6];
    const float* f_nw   = (const float*)d_in[7];
    const float* f_ow   = (const float*)d_in[8];
    const float* b_in_w = (const float*)d_in[9];
    const float* b_cw   = (const float*)d_in[10];
    const float* b_cb   = (const float*)d_in[11];
    const float* b_dtb  = (const float*)d_in[12];
    const float* b_Al   = (const float*)d_in[13];
    const float* b_Dp   = (const float*)d_in[14];
    const float* b_nw   = (const float*)d_in[15];
    const float* b_ow   = (const float*)d_in[16];
    float* out = (float*)d_out;

    const int nx  = MROWS * DMODEL / 4;
    const int nwi = DIP * DMODEL / 4;
    const int nwo = DMODEL * DINNER / 4;

    // ---- pre-round x + in-proj weights into dead scratch regions ----
    k_round<<<(nx  + 255) / 256, 256>>>(x,      0, nx);   // -> g_y alias
    k_round<<<(nwi + 255) / 256, 256>>>(f_in_w, 1, nwi);  // -> g_xBC alias
    k_round<<<(nwi + 255) / 256, 256>>>(b_in_w, 2, nwi);  // -> g_xBC alias

    dim3 gIn((DIP + 127) / 128, MROWS / 128, 2);          // 34 x 64 x 2
    k_inproj<<<gIn, 256>>>();

    dim3 gConv((CONVDIM + NHEADS + 255) / 256, MROWS, 2); // 9 x 8192 x 2
    k_conv<<<gConv, 256>>>(f_cw, f_cb, f_dtb, b_cw, b_cb, b_dtb);

    k_scan<<<dim3(NHEADS, BATCH, 2), HEADDIM>>>(f_Al, f_Dp, b_Al, b_Dp);

    // g_xBC fully consumed by k_scan -> reuse for rounded out-proj weights
    k_round<<<(nwo + 255) / 256, 256>>>(f_ow, 3, nwo);
    k_round<<<(nwo + 255) / 256, 256>>>(b_ow, 4, nwo);

    k_gate<<<dim3(MROWS, 2), 256>>>(f_nw, b_nw);

    dim3 gOut(DMODEL / 128, MROWS / 128);                 // 8 x 64
    k_outproj<<<gOut, 256>>>(out, 0, 0);
    k_outproj<<<gOut, 256>>>(out, 1, 1);
}

// round 7
// speedup vs baseline: 2.8374x; 1.3733x over previous
#include <cuda_runtime.h>
#include <math.h>
#include <stdint.h>

#define BATCH   4
#define SEQLEN  2048
#define DMODEL  1024
#define DINNER  2048
#define DSTATE  64
#define NHEADS  32
#define HEADDIM 64
#define CONVDIM 2176          // DINNER + 2*DSTATE
#define DIP     4256          // 2*DINNER + 2*DSTATE + NHEADS
#define MROWS   (BATCH*SEQLEN) // 8192
#define DTOFF   4224          // DINNER + CONVDIM

// ---- scratch (static device arrays; same footprint as passing builds) ----
__device__ float g_zx [2][MROWS][DIP];      // raw in-proj output
__device__ float g_xBC[2][MROWS][CONVDIM];  // ALIAS: tf32 in-proj W (before conv),
                                            //        tf32 out-proj W (after scan);
                                            // then post-conv+silu activations
__device__ float g_dt [2][NHEADS][MROWS];   // softplus(dt) TRANSPOSED (h-major)
__device__ float g_y  [2][MROWS][DINNER];   // ALIAS: tf32-rounded x (before scan);
                                            // then scan out -> gated/normed

__device__ __forceinline__ int fliprow(int m, int flip) {
    return flip ? ((m & ~(SEQLEN - 1)) | ((SEQLEN - 1) - (m & (SEQLEN - 1)))) : m;
}

__device__ __forceinline__ uint32_t f2tf32(float x) {
    uint32_t u;
    asm("cvt.rna.tf32.f32 %0, %1;" : "=r"(u) : "f"(x));
    return u;
}

// ---- packed f32x2 helpers (Blackwell) ----
typedef unsigned long long ull;
__device__ __forceinline__ ull pack2(float lo, float hi) {
    ull r; asm("mov.b64 %0, {%1, %2};" : "=l"(r) : "f"(lo), "f"(hi)); return r;
}
#define MUL2(d, a, b)    asm("mul.rn.f32x2 %0, %1, %2;" : "=l"(d) : "l"(a), "l"(b))
#define FMA2(d, a, b, c) asm("fma.rn.f32x2 %0, %1, %2, %3;" : "=l"(d) : "l"(a), "l"(b), "l"(c))
#define FMA2ACC(d, a, b) asm("fma.rn.f32x2 %0, %1, %2, %0;" : "+l"(d) : "l"(a), "l"(b))

// ============================================================================
// Pre-round fp32 -> tf32-precision fp32 into aliased scratch regions.
// ============================================================================
__global__ void __launch_bounds__(256)
k_round(const float* __restrict__ src, int which, int n4)
{
    float* dst;
    switch (which) {
        case 0:  dst = &g_y[0][0][0]; break;
        case 1:  dst = &g_xBC[0][0][0]; break;
        case 2:  dst = &g_xBC[0][0][0] + (size_t)DIP * DMODEL; break;
        case 3:  dst = &g_xBC[0][0][0]; break;
        default: dst = &g_xBC[0][0][0] + (size_t)DMODEL * DINNER; break;
    }
    const int i = blockIdx.x * blockDim.x + threadIdx.x;
    if (i < n4) {
        float4 v = ((const float4*)src)[i];
        v.x = __uint_as_float(f2tf32(v.x));
        v.y = __uint_as_float(f2tf32(v.y));
        v.z = __uint_as_float(f2tf32(v.z));
        v.w = __uint_as_float(f2tf32(v.w));
        ((float4*)dst)[i] = v;
    }
}

// ============================================================================
// tf32 tensor-core GEMM (unchanged from R6 passing build)
// ============================================================================
#define SPITCH 20

__device__ __forceinline__ void cp_async16(float* smem_dst, const float* gmem_src, int src_bytes) {
    uint32_t s = (uint32_t)__cvta_generic_to_shared(smem_dst);
    asm volatile("cp.async.cg.shared.global [%0], [%1], 16, %2;\n"
                 :: "r"(s), "l"(gmem_src), "r"(src_bytes));
}
__device__ __forceinline__ void cp_commit() { asm volatile("cp.async.commit_group;\n"); }
__device__ __forceinline__ void cp_wait0()  { asm volatile("cp.async.wait_group 0;\n"); }
__device__ __forceinline__ void cp_wait1()  { asm volatile("cp.async.wait_group 1;\n"); }

__device__ __forceinline__ void mma_16n8k8(float c[4], const uint32_t a[4], const uint32_t b[2]) {
    asm volatile("mma.sync.aligned.m16n8k8.row.col.f32.tf32.tf32.f32 "
                 "{%0,%1,%2,%3}, {%4,%5,%6,%7}, {%8,%9}, {%0,%1,%2,%3};"
                 : "+f"(c[0]), "+f"(c[1]), "+f"(c[2]), "+f"(c[3])
                 : "r"(a[0]), "r"(a[1]), "r"(a[2]), "r"(a[3]), "r"(b[0]), "r"(b[1]));
}

template<int N, int K>
__device__ __forceinline__ void tgemm_nt_body(
    const float* __restrict__ A, int flipA,
    const float* __restrict__ W,
    float* __restrict__ C, int accum)
{
    __shared__ float As[2][128][SPITCH];
    __shared__ float Bs[2][128][SPITCH];

    const int tid   = threadIdx.x;
    const int mBase = blockIdx.y * 128;
    const int nBase = blockIdx.x * 128;

    const int r0 = tid >> 2;
    const int kc = (tid & 3) * 4;

    const int amr0 = fliprow(mBase + r0, flipA);
    const int amr1 = fliprow(mBase + r0 + 64, flipA);
    const float* Ar0 = A + (size_t)amr0 * K + kc;
    const float* Ar1 = A + (size_t)amr1 * K + kc;
    const int wn0 = nBase + r0, wn1 = nBase + r0 + 64;
    const float* Wr0 = W + (size_t)wn0 * K + kc;
    const float* Wr1 = W + (size_t)wn1 * K + kc;
    const int wb0 = (wn0 < N) ? 16 : 0;
    const int wb1 = (wn1 < N) ? 16 : 0;

    const int lane = tid & 31;
    const int g    = lane >> 2;
    const int tig  = lane & 3;
    const int warp = tid >> 5;
    const int wm   = (warp & 1) * 64;
    const int wn   = (warp >> 1) * 32;

    float acc[4][4][4];
    #pragma unroll
    for (int mt = 0; mt < 4; mt++)
        #pragma unroll
        for (int nt = 0; nt < 4; nt++)
            #pragma unroll
            for (int c = 0; c < 4; c++) acc[mt][nt][c] = 0.f;

    cp_async16(&As[0][r0][kc],      Ar0, 16);
    cp_async16(&As[0][r0 + 64][kc], Ar1, 16);
    cp_async16(&Bs[0][r0][kc],      Wr0, wb0);
    cp_async16(&Bs[0][r0 + 64][kc], Wr1, wb1);
    cp_commit();

    constexpr int NT = K / 16;
    #pragma unroll 1
    for (int kt = 0; kt < NT; kt++) {
        cp_wait0();
        __syncthreads();

        if (kt + 1 < NT) {
            const int st = (kt + 1) & 1;
            const int ko = (kt + 1) * 16;
            cp_async16(&As[st][r0][kc],      Ar0 + ko, 16);
            cp_async16(&As[st][r0 + 64][kc], Ar1 + ko, 16);
            cp_async16(&Bs[st][r0][kc],      Wr0 + ko, wb0);
            cp_async16(&Bs[st][r0 + 64][kc], Wr1 + ko, wb1);
            cp_commit();
        }

        const int st = kt & 1;
        #pragma unroll
        for (int kk = 0; kk < 16; kk += 8) {
            uint32_t af[4][4], bf[4][2];
            #pragma unroll
            for (int mt = 0; mt < 4; mt++) {
                const int m0 = wm + mt * 16 + g;
                af[mt][0] = __float_as_uint(As[st][m0][kk + tig]);
                af[mt][1] = __float_as_uint(As[st][m0 + 8][kk + tig]);
                af[mt][2] = __float_as_uint(As[st][m0][kk + tig + 4]);
                af[mt][3] = __float_as_uint(As[st][m0 + 8][kk + tig + 4]);
            }
            #pragma unroll
            for (int nt = 0; nt < 4; nt++) {
                const int n0 = wn + nt * 8 + g;
                bf[nt][0] = __float_as_uint(Bs[st][n0][kk + tig]);
                bf[nt][1] = __float_as_uint(Bs[st][n0][kk + tig + 4]);
            }
            #pragma unroll
            for (int mt = 0; mt < 4; mt++)
                #pragma unroll
                for (int nt = 0; nt < 4; nt++)
                    mma_16n8k8(acc[mt][nt], af[mt], bf[nt]);
        }
        __syncthreads();
    }

    #pragma unroll
    for (int mt = 0; mt < 4; mt++) {
        const int m0 = mBase + wm + mt * 16 + g;
        float* crow0 = C + (size_t)m0 * N;
        float* crow1 = C + (size_t)(m0 + 8) * N;
        #pragma unroll
        for (int nt = 0; nt < 4; nt++) {
            const int n = nBase + wn + nt * 8 + tig * 2;
            if (n < N) {
                float2 v0 = make_float2(acc[mt][nt][0], acc[mt][nt][1]);
                float2 v1 = make_float2(acc[mt][nt][2], acc[mt][nt][3]);
                if (accum) {
                    float2 o0 = *(const float2*)(crow0 + n);
                    float2 o1 = *(const float2*)(crow1 + n);
                    v0.x += o0.x; v0.y += o0.y; v1.x += o1.x; v1.y += o1.y;
                }
                *(float2*)(crow0 + n) = v0;
                *(float2*)(crow1 + n) = v1;
            }
        }
    }
}

__global__ void __launch_bounds__(256)
k_inproj()
{
    const int dir = blockIdx.z;
    const float* xr  = &g_y[0][0][0];
    const float* win = &g_xBC[0][0][0] + (size_t)dir * DIP * DMODEL;
    tgemm_nt_body<DIP, DMODEL>(xr, dir, win, &g_zx[dir][0][0], 0);
}

__global__ void __launch_bounds__(256)
k_outproj(float* __restrict__ out, int dir, int accum)
{
    const float* wout = &g_xBC[0][0][0] + (size_t)dir * DMODEL * DINNER;
    tgemm_nt_body<DMODEL, DINNER>(&g_y[dir][0][0], dir, wout, out, accum);
}

// ============================================================================
// Depthwise causal conv (width 4) + bias + silu, fused with dt softplus.
// dt written TRANSPOSED: g_dt[dir][h][m].
// ============================================================================
__global__ void __launch_bounds__(256)
k_conv(const float* __restrict__ f_cw, const float* __restrict__ f_cb,
       const float* __restrict__ f_dtb,
       const float* __restrict__ b_cw, const float* __restrict__ b_cb,
       const float* __restrict__ b_dtb)
{
    const int c   = blockIdx.x * blockDim.x + threadIdx.x;
    const int m   = blockIdx.y;
    const int dir = blockIdx.z;
    const int l   = m & (SEQLEN - 1);

    if (c < CONVDIM) {
        const float* cw = dir ? b_cw : f_cw;
        const float* cb = dir ? b_cb : f_cb;
        float acc = cb[c];
        #pragma unroll
        for (int j = 0; j < 4; j++) {
            const int ls = l - 3 + j;
            if (ls >= 0)
                acc = fmaf(cw[c * 4 + j], g_zx[dir][m - 3 + j][DINNER + c], acc);
        }
        g_xBC[dir][m][c] = acc / (1.f + expf(-acc));
    } else if (c < CONVDIM + NHEADS) {
        const int h = c - CONVDIM;
        const float* dtb = dir ? b_dtb : f_dtb;
        const float v = g_zx[dir][m][DTOFF + h] + dtb[h];
        g_dt[dir][h][m] = (v > 20.f) ? v : log1pf(expf(v));
    }
}

// ============================================================================
// SSD scan v2: one CTA per (dir, batch, head); 64 threads (thread = headdim p).
// Chunked cp.async prefetch (8 steps/chunk, double-buffered) + packed f32x2.
// ============================================================================
#define SCHUNK 8
__global__ void __launch_bounds__(64)
k_scan(const float* __restrict__ fA, const float* __restrict__ fD,
       const float* __restrict__ bA, const float* __restrict__ bD)
{
    const int h = blockIdx.x, b = blockIdx.y, dir = blockIdx.z;
    const int tid = threadIdx.x;          // p = 0..63
    const float Ah = -expf((dir ? bA : fA)[h]);
    const float Dh = (dir ? bD : fD)[h];
    const int mBase = b * SEQLEN;

    __shared__ __align__(16) float sX[2][SCHUNK][64];
    __shared__ __align__(16) float sB[2][SCHUNK][64];
    __shared__ __align__(16) float sC[2][SCHUNK][64];
    __shared__ __align__(16) float sDt[2][SCHUNK];

    ull S2[32];
    #pragma unroll
    for (int i = 0; i < 32; i++) S2[i] = 0ull;

    // issue one chunk's loads (6 x 16B per thread + dt)
    auto issue = [&](int buf, int chunk) {
        #pragma unroll
        for (int j = 0; j < 6; j++) {
            const int idx = tid + 64 * j;       // 0..383
            const int region = idx >> 7;        // 0=x,1=B,2=C
            const int r = idx & 127;
            const int t = r >> 4;
            const int o = (r & 15) * 4;
            const float* row = &g_xBC[dir][mBase + chunk * SCHUNK + t][0];
            const float* src;
            float* dst;
            if (region == 0)      { src = row + h * HEADDIM + o;        dst = &sX[buf][t][o]; }
            else if (region == 1) { src = row + DINNER + o;             dst = &sB[buf][t][o]; }
            else                  { src = row + DINNER + DSTATE + o;    dst = &sC[buf][t][o]; }
            cp_async16(dst, src, 16);
        }
        if (tid < 2)
            cp_async16(&sDt[buf][tid * 4],
                       &g_dt[dir][h][mBase + chunk * SCHUNK + tid * 4], 16);
    };

    constexpr int NC = SEQLEN / SCHUNK;   // 256
    issue(0, 0);
    cp_commit();

    #pragma unroll 1
    for (int ch = 0; ch < NC; ch++) {
        const int buf = ch & 1;
        if (ch + 1 < NC) {
            issue(buf ^ 1, ch + 1);
            cp_commit();
            cp_wait1();                    // chunk ch's group complete
        } else {
            cp_wait0();
        }
        __syncthreads();

        #pragma unroll
        for (int t = 0; t < SCHUNK; t++) {
            const float dt = sDt[buf][t];
            const float dA = expf(dt * Ah);
            const float xp = sX[buf][t][tid];
            const float cf = dt * xp;
            const ull dA2 = pack2(dA, dA);
            const ull cf2 = pack2(cf, cf);

            ull y2[4] = {0ull, 0ull, 0ull, 0ull};
            #pragma unroll
            for (int q = 0; q < 16; q++) {
                const ulonglong2 bq = *(const ulonglong2*)&sB[buf][t][q * 4];
                const ulonglong2 cq = *(const ulonglong2*)&sC[buf][t][q * 4];
                ull tmp;
                MUL2(tmp, S2[2*q],   dA2); FMA2(S2[2*q],   cf2, bq.x, tmp);
                FMA2ACC(y2[(2*q)   & 3], S2[2*q],   cq.x);
                MUL2(tmp, S2[2*q+1], dA2); FMA2(S2[2*q+1], cf2, bq.y, tmp);
                FMA2ACC(y2[(2*q+1) & 3], S2[2*q+1], cq.y);
            }
            // horizontal sum of 4 packed accumulators
            float ys = 0.f;
            #pragma unroll
            for (int a = 0; a < 4; a++) {
                uint32_t lo, hi;
                asm("mov.b64 {%0, %1}, %2;" : "=r"(lo), "=r"(hi) : "l"(y2[a]));
                ys += __uint_as_float(lo) + __uint_as_float(hi);
            }
            g_y[dir][mBase + ch * SCHUNK + t][h * HEADDIM + tid] = ys + Dh * xp;
        }
        __syncthreads();
    }
}

// ============================================================================
// Gate with silu(z), RMSNorm over DINNER, scale by norm_w. In-place on g_y.
// Vectorized float4 I/O; output tf32-pre-rounded.
// ============================================================================
__global__ void __launch_bounds__(256)
k_gate(const float* __restrict__ fnw, const float* __restrict__ bnw)
{
    const int m = blockIdx.x, dir = blockIdx.y;
    const int tid = threadIdx.x;  // 256
    const float* nw = dir ? bnw : fnw;

    const float4* y4p = (const float4*)&g_y[dir][m][0];
    const float4* z4p = (const float4*)&g_zx[dir][m][0];

    float4 v[2];
    float ss = 0.f;
    #pragma unroll
    for (int i = 0; i < 2; i++) {
        const int idx = tid + i * 256;          // float4 index
        const float4 y4 = y4p[idx];
        const float4 z4 = z4p[idx];
        float4 r;
        r.x = y4.x * (z4.x / (1.f + expf(-z4.x)));
        r.y = y4.y * (z4.y / (1.f + expf(-z4.y)));
        r.z = y4.z * (z4.z / (1.f + expf(-z4.z)));
        r.w = y4.w * (z4.w / (1.f + expf(-z4.w)));
        v[i] = r;
        ss += r.x * r.x + r.y * r.y + r.z * r.z + r.w * r.w;
    }
    __shared__ float red[8];
    #pragma unroll
    for (int o = 16; o > 0; o >>= 1) ss += __shfl_xor_sync(0xffffffffu, ss, o);
    if ((tid & 31) == 0) red[tid >> 5] = ss;
    __syncthreads();
    if (tid < 8) {
        float t = red[tid];
        #pragma unroll
        for (int o = 4; o > 0; o >>= 1) t += __shfl_xor_sync(0xffu, t, o);
        if (tid == 0) red[0] = t;
    }
    __syncthreads();
    const float scale = rsqrtf(red[0] / (float)DINNER + 1e-5f);

    float4* o4p = (float4*)&g_y[dir][m][0];
    #pragma unroll
    for (int i = 0; i < 2; i++) {
        const int idx = tid + i * 256;
        const float4 w4 = ((const float4*)nw)[idx];
        float4 r = v[i];
        r.x = __uint_as_float(f2tf32(r.x * scale * w4.x));
        r.y = __uint_as_float(f2tf32(r.y * scale * w4.y));
        r.z = __uint_as_float(f2tf32(r.z * scale * w4.z));
        r.w = __uint_as_float(f2tf32(r.w * scale * w4.w));
        o4p[idx] = r;
    }
}

// ============================================================================
extern "C" void kernel_launch(void* const* d_in, const int* in_sizes, int n_in,
                              void* d_out, int out_size)
{
    (void)in_sizes; (void)n_in; (void)out_size;
    const float* x      = (const float*)d_in[0];
    const float* f_in_w = (const float*)d_in[1];
    const float* f_cw   = (const float*)d_in[2];
    const float* f_cb   = (const float*)d_in[3];
    const float* f_dtb  = (const float*)d_in[4];
    const float* f_Al   = (const float*)d_in[5];
    const float* f_Dp   = (const float*)d_in[6];
    const float* f_nw   = (const float*)d_in[7];
    const float* f_ow   = (const float*)d_in[8];
    const float* b_in_w = (const float*)d_in[9];
    const float* b_cw   = (const float*)d_in[10];
    const float* b_cb   = (const float*)d_in[11];
    const float* b_dtb  = (const float*)d_in[12];
    const float* b_Al   = (const float*)d_in[13];
    const float* b_Dp   = (const float*)d_in[14];
    const float* b_nw   = (const float*)d_in[15];
    const float* b_ow   = (const float*)d_in[16];
    float* out = (float*)d_out;

    const int nx  = MROWS * DMODEL / 4;
    const int nwi = DIP * DMODEL / 4;
    const int nwo = DMODEL * DINNER / 4;

    k_round<<<(nx  + 255) / 256, 256>>>(x,      0, nx);   // -> g_y alias
    k_round<<<(nwi + 255) / 256, 256>>>(f_in_w, 1, nwi);  // -> g_xBC alias
    k_round<<<(nwi + 255) / 256, 256>>>(b_in_w, 2, nwi);  // -> g_xBC alias

    dim3 gIn((DIP + 127) / 128, MROWS / 128, 2);
    k_inproj<<<gIn, 256>>>();

    dim3 gConv((CONVDIM + NHEADS + 255) / 256, MROWS, 2);
    k_conv<<<gConv, 256>>>(f_cw, f_cb, f_dtb, b_cw, b_cb, b_dtb);

    k_scan<<<dim3(NHEADS, BATCH, 2), HEADDIM>>>(f_Al, f_Dp, b_Al, b_Dp);

    // g_xBC fully consumed by k_scan -> reuse for rounded out-proj weights
    k_round<<<(nwo + 255) / 256, 256>>>(f_ow, 3, nwo);
    k_round<<<(nwo + 255) / 256, 256>>>(b_ow, 4, nwo);

    k_gate<<<dim3(MROWS, 2), 256>>>(f_nw, b_nw);

    dim3 gOut(DMODEL / 128, MROWS / 128);
    k_outproj<<<gOut, 256>>>(out, 0, 0);
    k_outproj<<<gOut, 256>>>(out, 1, 1);
}